// round 1
// baseline (speedup 1.0000x reference)
#include <cuda_runtime.h>

// Problem constants (fixed shapes from reference)
#define P_FULL   65536    // H*W
#define PN       12544    // sampled points
#define M_TGT    80       // targets
#define K_CLS    134      // classes
#define N_ROWS   400      // bs*Q
#define NT       256      // threads per block
#define PTS_PER_THREAD (PN / NT)   // 49 exactly

// Scratch (no allocations allowed): packed target bits per sampled point and y row sums.
__device__ uint4 g_ybits[PN];      // bits m=0..79 for each sampled point j
__device__ float g_ysum[M_TGT];    // sum_j y[m,j]

// ---------------------------------------------------------------------------
// Kernel 0a: zero ysum (graph-capturable, deterministic)
// ---------------------------------------------------------------------------
__global__ void hm_zero_kernel() {
    if (threadIdx.x < M_TGT) g_ysum[threadIdx.x] = 0.0f;
}

// ---------------------------------------------------------------------------
// Kernel 0b: build ybits[j] (80 bits per sampled point) and ysum[m].
// Grid: PN/NT blocks x NT threads, exactly one thread per sampled point.
// ---------------------------------------------------------------------------
__global__ void hm_prep_kernel(const float* __restrict__ tgt_masks,
                               const int*   __restrict__ point_idx) {
    int j  = blockIdx.x * blockDim.x + threadIdx.x;   // < PN by construction
    int pj = point_idx[j];

    unsigned w0 = 0u, w1 = 0u, w2 = 0u;
#pragma unroll
    for (int m = 0; m < 32; m++)
        if (tgt_masks[(size_t)m * P_FULL + pj] != 0.0f) w0 |= (1u << m);
#pragma unroll
    for (int m = 0; m < 32; m++)
        if (tgt_masks[(size_t)(32 + m) * P_FULL + pj] != 0.0f) w1 |= (1u << m);
#pragma unroll
    for (int m = 0; m < 16; m++)
        if (tgt_masks[(size_t)(64 + m) * P_FULL + pj] != 0.0f) w2 |= (1u << m);

    g_ybits[j] = make_uint4(w0, w1, w2, 0u);

    // Block-level count of set bits per m, then one global atomic per m per block.
    __shared__ int cnt[M_TGT];
    if (threadIdx.x < M_TGT) cnt[threadIdx.x] = 0;
    __syncthreads();

    int lane = threadIdx.x & 31;
#pragma unroll
    for (int m = 0; m < M_TGT; m++) {
        unsigned bit;
        if (m < 32)      bit = (w0 >> m) & 1u;
        else if (m < 64) bit = (w1 >> (m - 32)) & 1u;
        else             bit = (w2 >> (m - 64)) & 1u;
        unsigned ball = __ballot_sync(0xffffffffu, bit != 0u);
        if (lane == 0) atomicAdd(&cnt[m], __popc(ball));
    }
    __syncthreads();
    if (threadIdx.x < M_TGT)
        atomicAdd(&g_ysum[threadIdx.x], (float)cnt[threadIdx.x]);
}

// ---------------------------------------------------------------------------
// Main kernel: one CTA per n (row of pred_masks). Each thread processes 49
// sampled points, keeping 80 accx + 80 accs fp32 accumulators in registers.
// Binary y => predicated adds instead of FMAs.
// ---------------------------------------------------------------------------
__global__ void __launch_bounds__(NT, 1)
hm_main_kernel(const float* __restrict__ pred_logits,
               const float* __restrict__ pred_masks,
               const int*   __restrict__ tgt_labels,
               const int*   __restrict__ point_idx,
               float*       __restrict__ out) {
    const int n   = blockIdx.x;
    const int tid = threadIdx.x;
    const int lane = tid & 31;
    const float* __restrict__ xrow = pred_masks + (size_t)n * P_FULL;

    float accx[M_TGT];
    float accs[M_TGT];
#pragma unroll
    for (int m = 0; m < M_TGT; m++) { accx[m] = 0.0f; accs[m] = 0.0f; }
    float spsum = 0.0f, sgsum = 0.0f;

    // software pipeline: prefetch next point's x and ybits
    int   j  = tid;
    int   pj = point_idx[j];
    float x  = __ldg(xrow + pj);
    uint4 yb = g_ybits[j];

    for (int it = 0; it < PTS_PER_THREAD; it++) {
        float xc  = x;
        uint4 ybc = yb;
        int   jn  = j + NT;
        if (it + 1 < PTS_PER_THREAD) {
            int pjn = point_idx[jn];
            x  = __ldg(xrow + pjn);
            yb = g_ybits[jn];
        }
        j = jn;

        // softplus + sigmoid (stable, fast-math intrinsics OK for 1e-3 tol)
        float ax  = fabsf(xc);
        float e   = __expf(-ax);
        float sp  = fmaxf(xc, 0.0f) + __logf(1.0f + e);
        float inv = __fdividef(1.0f, 1.0f + e);
        float sg  = (xc >= 0.0f) ? inv : e * inv;
        spsum += sp;
        sgsum += sg;

        unsigned w = ybc.x;
#pragma unroll
        for (int m = 0; m < 32; m++) {
            if (w & (1u << m)) { accx[m] += xc; accs[m] += sg; }
        }
        w = ybc.y;
#pragma unroll
        for (int m = 0; m < 32; m++) {
            if (w & (1u << m)) { accx[32 + m] += xc; accs[32 + m] += sg; }
        }
        w = ybc.z;
#pragma unroll
        for (int m = 0; m < 16; m++) {
            if (w & (1u << m)) { accx[64 + m] += xc; accs[64 + m] += sg; }
        }
    }

    // ---- reduction across the CTA ----
    __shared__ float sx[M_TGT];
    __shared__ float ss[M_TGT];
    __shared__ float s_sp, s_sg;
    if (tid < M_TGT) { sx[tid] = 0.0f; ss[tid] = 0.0f; }
    if (tid == 0)    { s_sp = 0.0f; s_sg = 0.0f; }
    __syncthreads();

#pragma unroll
    for (int m = 0; m < M_TGT; m++) {
        float vx = accx[m];
        float vs = accs[m];
#pragma unroll
        for (int off = 16; off > 0; off >>= 1) {
            vx += __shfl_xor_sync(0xffffffffu, vx, off);
            vs += __shfl_xor_sync(0xffffffffu, vs, off);
        }
        if (lane == 0) {
            atomicAdd(&sx[m], vx);
            atomicAdd(&ss[m], vs);
        }
    }
    {
        float vp = spsum, vg = sgsum;
#pragma unroll
        for (int off = 16; off > 0; off >>= 1) {
            vp += __shfl_xor_sync(0xffffffffu, vp, off);
            vg += __shfl_xor_sync(0xffffffffu, vg, off);
        }
        if (lane == 0) {
            atomicAdd(&s_sp, vp);
            atomicAdd(&s_sg, vg);
        }
    }
    __syncthreads();

    // ---- epilogue: softmax over K=134 logits for this n, then cost matrix ----
    __shared__ float lg[K_CLS];
    __shared__ float red[2];
    if (tid < K_CLS) lg[tid] = pred_logits[(size_t)n * K_CLS + tid];
    __syncthreads();
    if (tid == 0) {
        float mx = -1e30f;
        for (int k = 0; k < K_CLS; k++) mx = fmaxf(mx, lg[k]);
        float sm = 0.0f;
        for (int k = 0; k < K_CLS; k++) sm += __expf(lg[k] - mx);
        red[0] = mx;
        red[1] = __fdividef(1.0f, sm);
    }
    __syncthreads();
    if (tid < K_CLS) lg[tid] = __expf(lg[tid] - red[0]) * red[1];
    __syncthreads();

    if (tid < M_TGT) {
        int lbl = tgt_labels[tid];
        lbl = min(max(lbl, 0), K_CLS - 1);
        float p  = lg[lbl];
        float xy = sx[tid];
        float sy = ss[tid];
        const float invPn = 1.0f / (float)PN;
        float cost_class = -p;
        float cost_mask  = s_sp * invPn - xy * invPn;
        float cost_dice  = 1.0f - (2.0f * sy + 1.0f) /
                                  (s_sg + g_ysum[tid] + 1.0f);
        out[(size_t)n * M_TGT + tid] =
            2.0f * cost_class + 5.0f * cost_mask + 5.0f * cost_dice;
    }
}

// ---------------------------------------------------------------------------
// Entry point. Inputs (metadata order):
//   d_in[0] pred_logits f32 (4,100,134)
//   d_in[1] pred_masks  f32 (4,100,256,256)
//   d_in[2] tgt_labels  i32 (80)
//   d_in[3] tgt_masks   f32 (80,256,256)
//   d_in[4] point_idx   i32 (12544)
// out: f32 (4,100,80)
// ---------------------------------------------------------------------------
extern "C" void kernel_launch(void* const* d_in, const int* in_sizes, int n_in,
                              void* d_out, int out_size) {
    const float* pred_logits = (const float*)d_in[0];
    const float* pred_masks  = (const float*)d_in[1];
    const int*   tgt_labels  = (const int*)  d_in[2];
    const float* tgt_masks   = (const float*)d_in[3];
    const int*   point_idx   = (const int*)  d_in[4];
    float* out = (float*)d_out;

    hm_zero_kernel<<<1, 128>>>();
    hm_prep_kernel<<<PN / NT, NT>>>(tgt_masks, point_idx);
    hm_main_kernel<<<N_ROWS, NT>>>(pred_logits, pred_masks, tgt_labels,
                                   point_idx, out);
}

// round 2
// speedup vs baseline: 1.1437x; 1.1437x over previous
#include <cuda_runtime.h>

// Fixed problem shapes
#define P_FULL   65536    // H*W
#define PN       12544    // sampled points
#define M_TGT    80       // targets
#define K_CLS    134      // classes
#define N_ROWS   400      // bs*Q
#define NT       256      // threads per block
#define NBLK_PREP (PN / NT)          // 49
#define PTS_PER_THREAD (PN / NT)     // 49

// Static scratch (no allocations allowed)
__device__ uint4 g_ybits[PN];              // bits m=0..79 per sampled point
__device__ int   g_ycnt[NBLK_PREP * M_TGT]; // per-prep-block popcounts

// ---------------------------------------------------------------------------
// 8-bit-slot predicated packed accumulate:
//   for i in 0..7: if (w>>i)&1 then acc[i] (f32x2) += xs (f32x2)
// 1 LOP3(pred-out) + 1 predicated add.rn.f32x2 per slot.
// ---------------------------------------------------------------------------
__device__ __forceinline__ void acc8(unsigned long long* a, unsigned wv,
                                     unsigned long long xs) {
    asm volatile(
        "{\n\t"
        ".reg .pred q,p0,p1,p2,p3,p4,p5,p6,p7;\n\t"
        ".reg .b32 t;\n\t"
        "setp.eq.u32 q, %8, %8;\n\t"
        "lop3.and.b32 t|p0, %8, 0x1,  0, 0xC0, q;\n\t"
        "lop3.and.b32 t|p1, %8, 0x2,  0, 0xC0, q;\n\t"
        "lop3.and.b32 t|p2, %8, 0x4,  0, 0xC0, q;\n\t"
        "lop3.and.b32 t|p3, %8, 0x8,  0, 0xC0, q;\n\t"
        "lop3.and.b32 t|p4, %8, 0x10, 0, 0xC0, q;\n\t"
        "lop3.and.b32 t|p5, %8, 0x20, 0, 0xC0, q;\n\t"
        "lop3.and.b32 t|p6, %8, 0x40, 0, 0xC0, q;\n\t"
        "lop3.and.b32 t|p7, %8, 0x80, 0, 0xC0, q;\n\t"
        "@p0 add.rn.f32x2 %0, %0, %9;\n\t"
        "@p1 add.rn.f32x2 %1, %1, %9;\n\t"
        "@p2 add.rn.f32x2 %2, %2, %9;\n\t"
        "@p3 add.rn.f32x2 %3, %3, %9;\n\t"
        "@p4 add.rn.f32x2 %4, %4, %9;\n\t"
        "@p5 add.rn.f32x2 %5, %5, %9;\n\t"
        "@p6 add.rn.f32x2 %6, %6, %9;\n\t"
        "@p7 add.rn.f32x2 %7, %7, %9;\n\t"
        "}\n\t"
        : "+l"(a[0]), "+l"(a[1]), "+l"(a[2]), "+l"(a[3]),
          "+l"(a[4]), "+l"(a[5]), "+l"(a[6]), "+l"(a[7])
        : "r"(wv), "l"(xs));
}

// ---------------------------------------------------------------------------
// Prep: build ybits[j] and per-block popcounts (no atomics, no zero kernel).
// Grid: 49 blocks x 256 threads, one thread per sampled point.
// ---------------------------------------------------------------------------
__global__ void hm_prep_kernel(const float* __restrict__ tgt_masks,
                               const int*   __restrict__ point_idx) {
    int tid = threadIdx.x;
    int j   = blockIdx.x * NT + tid;
    int pj  = point_idx[j];

    unsigned w0 = 0u, w1 = 0u, w2 = 0u;
#pragma unroll
    for (int m = 0; m < 32; m++)
        if (__ldg(tgt_masks + (size_t)m * P_FULL + pj) != 0.0f) w0 |= (1u << m);
#pragma unroll
    for (int m = 0; m < 32; m++)
        if (__ldg(tgt_masks + (size_t)(32 + m) * P_FULL + pj) != 0.0f) w1 |= (1u << m);
#pragma unroll
    for (int m = 0; m < 16; m++)
        if (__ldg(tgt_masks + (size_t)(64 + m) * P_FULL + pj) != 0.0f) w2 |= (1u << m);

    g_ybits[j] = make_uint4(w0, w1, w2, 0u);

    __shared__ int cnt[M_TGT];
    if (tid < M_TGT) cnt[tid] = 0;
    __syncthreads();

    int lane = tid & 31;
#pragma unroll
    for (int m = 0; m < M_TGT; m++) {
        unsigned bit;
        if (m < 32)      bit = (w0 >> m) & 1u;
        else if (m < 64) bit = (w1 >> (m - 32)) & 1u;
        else             bit = (w2 >> (m - 64)) & 1u;
        unsigned ball = __ballot_sync(0xffffffffu, bit != 0u);
        if (lane == 0) atomicAdd(&cnt[m], __popc(ball));
    }
    __syncthreads();
    if (tid < M_TGT) g_ycnt[blockIdx.x * M_TGT + tid] = cnt[tid];
}

// ---------------------------------------------------------------------------
// Main kernel: one CTA per n. 80 packed (x-sum, sg-sum) f32x2 accumulators
// per thread; 49 points per thread; LOP3-pred + FADD2 inner loop.
// ---------------------------------------------------------------------------
__global__ void __launch_bounds__(NT, 1)
hm_main_kernel(const float* __restrict__ pred_logits,
               const float* __restrict__ pred_masks,
               const int*   __restrict__ tgt_labels,
               const int*   __restrict__ point_idx,
               float*       __restrict__ out) {
    const int n    = blockIdx.x;
    const int tid  = threadIdx.x;
    const int lane = tid & 31;
    const float* __restrict__ xrow = pred_masks + (size_t)n * P_FULL;

    unsigned long long acc[M_TGT];
#pragma unroll
    for (int m = 0; m < M_TGT; m++) acc[m] = 0ull;
    float spsum = 0.0f, sgsum = 0.0f;

    // prefetch pipeline (1 deep)
    int   j  = tid;
    int   pj = __ldg(point_idx + j);
    float x  = __ldg(xrow + pj);
    uint4 yb = g_ybits[j];

    for (int it = 0; it < PTS_PER_THREAD; it++) {
        float xc  = x;
        uint4 ybc = yb;
        int   jn  = j + NT;
        if (it + 1 < PTS_PER_THREAD) {
            int pjn = __ldg(point_idx + jn);
            x  = __ldg(xrow + pjn);
            yb = g_ybits[jn];
        }
        j = jn;

        // softplus + sigmoid (stable)
        float ax  = fabsf(xc);
        float e   = __expf(-ax);
        float sp  = fmaxf(xc, 0.0f) + __logf(1.0f + e);
        float inv = __fdividef(1.0f, 1.0f + e);
        float sg  = (xc >= 0.0f) ? inv : e * inv;
        spsum += sp;
        sgsum += sg;

        unsigned long long xs;
        asm("mov.b64 %0, {%1, %2};" : "=l"(xs) : "f"(xc), "f"(sg));

        acc8(acc +  0, ybc.x,       xs);
        acc8(acc +  8, ybc.x >> 8,  xs);
        acc8(acc + 16, ybc.x >> 16, xs);
        acc8(acc + 24, ybc.x >> 24, xs);
        acc8(acc + 32, ybc.y,       xs);
        acc8(acc + 40, ybc.y >> 8,  xs);
        acc8(acc + 48, ybc.y >> 16, xs);
        acc8(acc + 56, ybc.y >> 24, xs);
        acc8(acc + 64, ybc.z,       xs);
        acc8(acc + 72, ybc.z >> 8,  xs);
    }

    // ---- CTA reduction ----
    __shared__ float sx[M_TGT];
    __shared__ float ss[M_TGT];
    __shared__ float s_sp, s_sg;
    if (tid < M_TGT) { sx[tid] = 0.0f; ss[tid] = 0.0f; }
    if (tid == 0)    { s_sp = 0.0f; s_sg = 0.0f; }
    __syncthreads();

#pragma unroll
    for (int m = 0; m < M_TGT; m++) {
        float vx = __uint_as_float((unsigned)(acc[m] & 0xffffffffull));
        float vs = __uint_as_float((unsigned)(acc[m] >> 32));
#pragma unroll
        for (int off = 16; off > 0; off >>= 1) {
            vx += __shfl_xor_sync(0xffffffffu, vx, off);
            vs += __shfl_xor_sync(0xffffffffu, vs, off);
        }
        if (lane == 0) {
            atomicAdd(&sx[m], vx);
            atomicAdd(&ss[m], vs);
        }
    }
    {
        float vp = spsum, vg = sgsum;
#pragma unroll
        for (int off = 16; off > 0; off >>= 1) {
            vp += __shfl_xor_sync(0xffffffffu, vp, off);
            vg += __shfl_xor_sync(0xffffffffu, vg, off);
        }
        if (lane == 0) {
            atomicAdd(&s_sp, vp);
            atomicAdd(&s_sg, vg);
        }
    }
    __syncthreads();

    // ---- epilogue: softmax over K=134, assemble costs ----
    __shared__ float lg[K_CLS];
    __shared__ float red[2];
    if (tid < K_CLS) lg[tid] = pred_logits[(size_t)n * K_CLS + tid];
    __syncthreads();
    if (tid == 0) {
        float mx = -1e30f;
        for (int k = 0; k < K_CLS; k++) mx = fmaxf(mx, lg[k]);
        float sm = 0.0f;
        for (int k = 0; k < K_CLS; k++) sm += __expf(lg[k] - mx);
        red[0] = mx;
        red[1] = __fdividef(1.0f, sm);
    }
    __syncthreads();
    if (tid < K_CLS) lg[tid] = __expf(lg[tid] - red[0]) * red[1];
    __syncthreads();

    if (tid < M_TGT) {
        float ysum = 0.0f;
#pragma unroll
        for (int b = 0; b < NBLK_PREP; b++)
            ysum += (float)g_ycnt[b * M_TGT + tid];

        int lbl = tgt_labels[tid];
        lbl = min(max(lbl, 0), K_CLS - 1);
        float p  = lg[lbl];
        float xy = sx[tid];
        float sy = ss[tid];
        const float invPn = 1.0f / (float)PN;
        float cost_class = -p;
        float cost_mask  = (s_sp - xy) * invPn;
        float cost_dice  = 1.0f - (2.0f * sy + 1.0f) / (s_sg + ysum + 1.0f);
        out[(size_t)n * M_TGT + tid] =
            2.0f * cost_class + 5.0f * cost_mask + 5.0f * cost_dice;
    }
}

// ---------------------------------------------------------------------------
// Inputs (metadata order):
//   d_in[0] pred_logits f32 (4,100,134)
//   d_in[1] pred_masks  f32 (4,100,256,256)
//   d_in[2] tgt_labels  i32 (80)
//   d_in[3] tgt_masks   f32 (80,256,256)
//   d_in[4] point_idx   i32 (12544)
// out: f32 (4,100,80)
// ---------------------------------------------------------------------------
extern "C" void kernel_launch(void* const* d_in, const int* in_sizes, int n_in,
                              void* d_out, int out_size) {
    const float* pred_logits = (const float*)d_in[0];
    const float* pred_masks  = (const float*)d_in[1];
    const int*   tgt_labels  = (const int*)  d_in[2];
    const float* tgt_masks   = (const float*)d_in[3];
    const int*   point_idx   = (const int*)  d_in[4];
    float* out = (float*)d_out;

    hm_prep_kernel<<<NBLK_PREP, NT>>>(tgt_masks, point_idx);
    hm_main_kernel<<<N_ROWS, NT>>>(pred_logits, pred_masks, tgt_labels,
                                   point_idx, out);
}

// round 3
// speedup vs baseline: 1.4744x; 1.2892x over previous
#include <cuda_runtime.h>

// Fixed problem shapes
#define P_FULL   65536    // H*W
#define PN       12544    // sampled points
#define M_TGT    80       // targets
#define K_CLS    134      // classes
#define N_ROWS   400      // bs*Q
#define NT       256      // threads per block
#define NBLK_PREP (PN / NT)          // 49
#define NGROUPS  (PN / 4)            // 3136 groups of 4 points
#define GPT      (NGROUPS / NT)      // 12 base groups/thread (+1 for tid<64)
#define GREM     (NGROUPS - GPT * NT) // 64

typedef unsigned long long ull;

// Static scratch
__device__ uint4 g_ybits[PN];               // 80 target bits per sampled point
__device__ unsigned g_pat[NGROUPS][12];     // nibble patterns per group (10 used, padded to 48B rows)
__device__ int   g_ycnt[NBLK_PREP * M_TGT]; // per-prep-block popcounts

// ---------- f32x2 helpers ----------
__device__ __forceinline__ ull f2pack(float a, float b) {
    ull r; asm("mov.b64 %0, {%1, %2};" : "=l"(r) : "f"(a), "f"(b)); return r;
}
__device__ __forceinline__ ull add2(ull a, ull b) {
    ull r; asm("add.rn.f32x2 %0, %1, %2;" : "=l"(r) : "l"(a), "l"(b)); return r;
}

// spread 8 bits so bit k lands at position 4k
__device__ __forceinline__ unsigned expand8(unsigned v) {
    v = (v | (v << 12)) & 0x000F000Fu;
    v = (v | (v << 6))  & 0x03030303u;
    v = (v | (v << 3))  & 0x11111111u;
    return v;
}

// ---------------------------------------------------------------------------
// Prep 1: per-point 80-bit target masks + per-block popcounts.
// ---------------------------------------------------------------------------
__global__ void hm_prep1_kernel(const float* __restrict__ tgt_masks,
                                const int*   __restrict__ point_idx) {
    int tid = threadIdx.x;
    int j   = blockIdx.x * NT + tid;
    int pj  = point_idx[j];

    unsigned w0 = 0u, w1 = 0u, w2 = 0u;
#pragma unroll
    for (int m = 0; m < 32; m++)
        if (__ldg(tgt_masks + (size_t)m * P_FULL + pj) != 0.0f) w0 |= (1u << m);
#pragma unroll
    for (int m = 0; m < 32; m++)
        if (__ldg(tgt_masks + (size_t)(32 + m) * P_FULL + pj) != 0.0f) w1 |= (1u << m);
#pragma unroll
    for (int m = 0; m < 16; m++)
        if (__ldg(tgt_masks + (size_t)(64 + m) * P_FULL + pj) != 0.0f) w2 |= (1u << m);

    g_ybits[j] = make_uint4(w0, w1, w2, 0u);

    __shared__ int cnt[M_TGT];
    if (tid < M_TGT) cnt[tid] = 0;
    __syncthreads();
    int lane = tid & 31;
#pragma unroll
    for (int m = 0; m < M_TGT; m++) {
        unsigned bit;
        if (m < 32)      bit = (w0 >> m) & 1u;
        else if (m < 64) bit = (w1 >> (m - 32)) & 1u;
        else             bit = (w2 >> (m - 64)) & 1u;
        unsigned ball = __ballot_sync(0xffffffffu, bit != 0u);
        if (lane == 0) atomicAdd(&cnt[m], __popc(ball));
    }
    __syncthreads();
    if (tid < M_TGT) g_ycnt[blockIdx.x * M_TGT + tid] = cnt[tid];
}

// ---------------------------------------------------------------------------
// Prep 2: interleave y bits of each 4-point group into nibble pattern words.
// word w of group g holds, at bits [4k,4k+4), the 4-point pattern of m=8w+k.
// ---------------------------------------------------------------------------
__global__ void hm_prep2_kernel() {
    int g = blockIdx.x * blockDim.x + threadIdx.x;
    if (g >= NGROUPS) return;
    uint4 a = g_ybits[4 * g + 0];
    uint4 b = g_ybits[4 * g + 1];
    uint4 c = g_ybits[4 * g + 2];
    uint4 d = g_ybits[4 * g + 3];

#pragma unroll
    for (int w = 0; w < 10; w++) {
        unsigned ba, bb, bc, bd;
        if (w < 4) {
            ba = (a.x >> (8 * w)) & 0xFFu; bb = (b.x >> (8 * w)) & 0xFFu;
            bc = (c.x >> (8 * w)) & 0xFFu; bd = (d.x >> (8 * w)) & 0xFFu;
        } else if (w < 8) {
            ba = (a.y >> (8 * (w - 4))) & 0xFFu; bb = (b.y >> (8 * (w - 4))) & 0xFFu;
            bc = (c.y >> (8 * (w - 4))) & 0xFFu; bd = (d.y >> (8 * (w - 4))) & 0xFFu;
        } else {
            ba = (a.z >> (8 * (w - 8))) & 0xFFu; bb = (b.z >> (8 * (w - 8))) & 0xFFu;
            bc = (c.z >> (8 * (w - 8))) & 0xFFu; bd = (d.z >> (8 * (w - 8))) & 0xFFu;
        }
        g_pat[g][w] = expand8(ba) | (expand8(bb) << 1) |
                      (expand8(bc) << 2) | (expand8(bd) << 3);
    }
    g_pat[g][10] = 0u; g_pat[g][11] = 0u;
}

// ---------------------------------------------------------------------------
// Main kernel: one CTA per n. Four-Russians: per 4-point group build the 16
// subset sums of packed (x, sigmoid) f32x2 in a per-thread smem LUT, then one
// LDS.64 + FADD2 per (group, target).
// ---------------------------------------------------------------------------
__global__ void __launch_bounds__(NT, 1)
hm_main_kernel(const float* __restrict__ pred_logits,
               const float* __restrict__ pred_masks,
               const int*   __restrict__ tgt_labels,
               const int*   __restrict__ point_idx,
               float*       __restrict__ out) {
    const int n    = blockIdx.x;
    const int tid  = threadIdx.x;
    const int lane = tid & 31;
    const float* __restrict__ xrow = pred_masks + (size_t)n * P_FULL;

    // Per-thread subset LUT: lut[nib*NT + tid] -> bank = 2*tid (conflict-free)
    __shared__ ull lut[16 * NT];

    ull acc[M_TGT];
#pragma unroll
    for (int m = 0; m < M_TGT; m++) acc[m] = 0ull;
    float spsum = 0.0f, sgsum = 0.0f;

    const int niter = (tid < GREM) ? (GPT + 1) : GPT;

    // prefetch first group's gathers
    int4  pidx = __ldg((const int4*)point_idx + tid);
    float nx0 = __ldg(xrow + pidx.x);
    float nx1 = __ldg(xrow + pidx.y);
    float nx2 = __ldg(xrow + pidx.z);
    float nx3 = __ldg(xrow + pidx.w);

#pragma unroll 1
    for (int i = 0; i < niter; i++) {
        const int g = tid + i * NT;
        float x0 = nx0, x1 = nx1, x2 = nx2, x3 = nx3;
        if (i + 1 < niter) {
            int4 np = __ldg((const int4*)point_idx + (g + NT));
            nx0 = __ldg(xrow + np.x);
            nx1 = __ldg(xrow + np.y);
            nx2 = __ldg(xrow + np.z);
            nx3 = __ldg(xrow + np.w);
        }

        // activations
        float sg0, sg1, sg2, sg3, sp;
        {
            float ax, e, inv;
            ax = fabsf(x0); e = __expf(-ax); inv = __fdividef(1.f, 1.f + e);
            sg0 = (x0 >= 0.f) ? inv : e * inv;
            sp  = fmaxf(x0, 0.f) + __logf(1.f + e);
            ax = fabsf(x1); e = __expf(-ax); inv = __fdividef(1.f, 1.f + e);
            sg1 = (x1 >= 0.f) ? inv : e * inv;
            sp += fmaxf(x1, 0.f) + __logf(1.f + e);
            ax = fabsf(x2); e = __expf(-ax); inv = __fdividef(1.f, 1.f + e);
            sg2 = (x2 >= 0.f) ? inv : e * inv;
            sp += fmaxf(x2, 0.f) + __logf(1.f + e);
            ax = fabsf(x3); e = __expf(-ax); inv = __fdividef(1.f, 1.f + e);
            sg3 = (x3 >= 0.f) ? inv : e * inv;
            sp += fmaxf(x3, 0.f) + __logf(1.f + e);
        }
        spsum += sp;
        sgsum += sg0 + sg1 + sg2 + sg3;

        // 16 subset sums of the 4 packed (x, sg) values (11 FADD2)
        {
            ull p0 = f2pack(x0, sg0), p1 = f2pack(x1, sg1);
            ull p2 = f2pack(x2, sg2), p3 = f2pack(x3, sg3);
            ull s3  = add2(p0, p1);
            ull s5  = add2(p2, p0), s6 = add2(p2, p1), s7 = add2(p2, s3);
            ull s9  = add2(p3, p0), s10 = add2(p3, p1), s11 = add2(p3, s3);
            ull s12 = add2(p3, p2), s13 = add2(p3, s5), s14 = add2(p3, s6);
            ull s15 = add2(p3, s7);
            lut[0 * NT + tid]  = 0ull;
            lut[1 * NT + tid]  = p0;  lut[2 * NT + tid]  = p1;
            lut[3 * NT + tid]  = s3;  lut[4 * NT + tid]  = p2;
            lut[5 * NT + tid]  = s5;  lut[6 * NT + tid]  = s6;
            lut[7 * NT + tid]  = s7;  lut[8 * NT + tid]  = p3;
            lut[9 * NT + tid]  = s9;  lut[10 * NT + tid] = s10;
            lut[11 * NT + tid] = s11; lut[12 * NT + tid] = s12;
            lut[13 * NT + tid] = s13; lut[14 * NT + tid] = s14;
            lut[15 * NT + tid] = s15;
        }
        // per-thread LUT: same-thread read-after-write, no barrier needed

        // pattern words (3x uint4, rows padded to 48B)
        uint4 pa = __ldg((const uint4*)&g_pat[g][0]);
        uint4 pb = __ldg((const uint4*)&g_pat[g][4]);
        uint4 pc = __ldg((const uint4*)&g_pat[g][8]);
        unsigned pw[10] = {pa.x, pa.y, pa.z, pa.w, pb.x, pb.y, pb.z, pb.w,
                           pc.x, pc.y};

#pragma unroll
        for (int w = 0; w < 10; w++) {
            unsigned word = pw[w];
#pragma unroll
            for (int k = 0; k < 8; k++) {
                unsigned nib = (word >> (4 * k)) & 0xFu;
                ull v = lut[(nib << 8) + (unsigned)tid];
                acc[8 * w + k] = add2(acc[8 * w + k], v);
            }
        }
    }

    // ---- CTA reduction ----
    __shared__ float sx[M_TGT];
    __shared__ float ss[M_TGT];
    __shared__ float s_sp, s_sg;
    if (tid < M_TGT) { sx[tid] = 0.0f; ss[tid] = 0.0f; }
    if (tid == 0)    { s_sp = 0.0f; s_sg = 0.0f; }
    __syncthreads();

#pragma unroll
    for (int m = 0; m < M_TGT; m++) {
        float vx = __uint_as_float((unsigned)(acc[m] & 0xffffffffull));
        float vs = __uint_as_float((unsigned)(acc[m] >> 32));
#pragma unroll
        for (int off = 16; off > 0; off >>= 1) {
            vx += __shfl_xor_sync(0xffffffffu, vx, off);
            vs += __shfl_xor_sync(0xffffffffu, vs, off);
        }
        if (lane == 0) {
            atomicAdd(&sx[m], vx);
            atomicAdd(&ss[m], vs);
        }
    }
    {
        float vp = spsum, vg = sgsum;
#pragma unroll
        for (int off = 16; off > 0; off >>= 1) {
            vp += __shfl_xor_sync(0xffffffffu, vp, off);
            vg += __shfl_xor_sync(0xffffffffu, vg, off);
        }
        if (lane == 0) {
            atomicAdd(&s_sp, vp);
            atomicAdd(&s_sg, vg);
        }
    }
    __syncthreads();

    // ---- epilogue: softmax over K=134, assemble costs ----
    __shared__ float lg[K_CLS];
    __shared__ float red[2];
    if (tid < K_CLS) lg[tid] = pred_logits[(size_t)n * K_CLS + tid];
    __syncthreads();
    if (tid == 0) {
        float mx = -1e30f;
        for (int k = 0; k < K_CLS; k++) mx = fmaxf(mx, lg[k]);
        float sm = 0.0f;
        for (int k = 0; k < K_CLS; k++) sm += __expf(lg[k] - mx);
        red[0] = mx;
        red[1] = __fdividef(1.0f, sm);
    }
    __syncthreads();
    if (tid < K_CLS) lg[tid] = __expf(lg[tid] - red[0]) * red[1];
    __syncthreads();

    if (tid < M_TGT) {
        float ysum = 0.0f;
#pragma unroll
        for (int b = 0; b < NBLK_PREP; b++)
            ysum += (float)g_ycnt[b * M_TGT + tid];

        int lbl = tgt_labels[tid];
        lbl = min(max(lbl, 0), K_CLS - 1);
        float p  = lg[lbl];
        float xy = sx[tid];
        float sy = ss[tid];
        const float invPn = 1.0f / (float)PN;
        float cost_class = -p;
        float cost_mask  = (s_sp - xy) * invPn;
        float cost_dice  = 1.0f - (2.0f * sy + 1.0f) / (s_sg + ysum + 1.0f);
        out[(size_t)n * M_TGT + tid] =
            2.0f * cost_class + 5.0f * cost_mask + 5.0f * cost_dice;
    }
}

// ---------------------------------------------------------------------------
// Inputs (metadata order):
//   d_in[0] pred_logits f32 (4,100,134)
//   d_in[1] pred_masks  f32 (4,100,256,256)
//   d_in[2] tgt_labels  i32 (80)
//   d_in[3] tgt_masks   f32 (80,256,256)
//   d_in[4] point_idx   i32 (12544)
// out: f32 (4,100,80)
// ---------------------------------------------------------------------------
extern "C" void kernel_launch(void* const* d_in, const int* in_sizes, int n_in,
                              void* d_out, int out_size) {
    const float* pred_logits = (const float*)d_in[0];
    const float* pred_masks  = (const float*)d_in[1];
    const int*   tgt_labels  = (const int*)  d_in[2];
    const float* tgt_masks   = (const float*)d_in[3];
    const int*   point_idx   = (const int*)  d_in[4];
    float* out = (float*)d_out;

    hm_prep1_kernel<<<NBLK_PREP, NT>>>(tgt_masks, point_idx);
    hm_prep2_kernel<<<(NGROUPS + 127) / 128, 128>>>();
    hm_main_kernel<<<N_ROWS, NT>>>(pred_logits, pred_masks, tgt_labels,
                                   point_idx, out);
}